// round 9
// baseline (speedup 1.0000x reference)
#include <cuda_runtime.h>
#include <cstdint>

// Problem constants
constexpr int T_ = 1024;
constexpr int B_ = 32;
constexpr int D_ = 1024;
constexpr int M_ = T_ * B_;        // 32768 rows for the precompute GEMMs

// Scratch for precomputed xRx ([0]) and xWd ([1])
__device__ float g_scratch[2][(size_t)M_ * D_];

// ---------------------------------------------------------------------------
// Packed f32x2 helpers (sm_103a): one instruction = two fp32 FMAs/ADDs.
// ---------------------------------------------------------------------------
__device__ __forceinline__ void fma2(unsigned long long& d,
                                     unsigned long long a,
                                     unsigned long long b) {
    asm("fma.rn.f32x2 %0, %1, %2, %0;" : "+l"(d) : "l"(a), "l"(b));
}
__device__ __forceinline__ void add2(unsigned long long& d,
                                     unsigned long long a) {
    asm("add.rn.f32x2 %0, %0, %1;" : "+l"(d) : "l"(a));
}
__device__ __forceinline__ unsigned long long dup2(float x) {
    unsigned long long r;
    asm("mov.b64 %0, {%1, %1};" : "=l"(r) : "f"(x));
    return r;
}
__device__ __forceinline__ float2 unpk(unsigned long long v) {
    float2 r;
    asm("mov.b64 {%0, %1}, %2;" : "=f"(r.x), "=f"(r.y) : "l"(v));
    return r;
}

// ---------------------------------------------------------------------------
// Precompute GEMM: C[m][n] = sum_k A[m][k] * W[n][k] + bias[n]
// 128x128 tile, k-tile 8, 256 threads, 8x8 microtile held as 8x4 f32x2
// packed accumulators, double-buffered SMEM. blockIdx.z selects the
// (W, bias, C) pair so both GEMMs share A through L2.
// ---------------------------------------------------------------------------
constexpr int BM = 128, BN = 128, BK = 8;

__global__ void __launch_bounds__(256) gemm_bias_kernel(
    const float* __restrict__ A,
    const float* __restrict__ W0, const float* __restrict__ W1,
    const float* __restrict__ b0, const float* __restrict__ b1)
{
    const float* __restrict__ W    = blockIdx.z ? W1 : W0;
    const float* __restrict__ bias = blockIdx.z ? b1 : b0;
    float* __restrict__ C = g_scratch[blockIdx.z];

    __shared__ float As[2][BK][BM];
    __shared__ float Ws[2][BK][BN];

    const int m0 = blockIdx.y * BM;
    const int n0 = blockIdx.x * BN;
    const int tid = threadIdx.x;

    const int lrow = tid >> 1;            // 0..127
    const int lk   = (tid & 1) << 2;      // 0 or 4

    const int wid  = tid >> 5;
    const int lane = tid & 31;
    const int wm   = (wid & 3) * 32;
    const int wn   = (wid >> 2) * 64;
    const int trow = (lane >> 3) << 2;    // 0,4,8,12
    const int tcol = (lane & 7) << 2;     // 0..28

    unsigned long long acc2[8][4];
#pragma unroll
    for (int i = 0; i < 8; i++)
#pragma unroll
        for (int p = 0; p < 4; p++) acc2[i][p] = 0ull;

    const float* Aptr = A + (size_t)(m0 + lrow) * D_ + lk;
    const float* Wptr = W + (size_t)(n0 + lrow) * D_ + lk;

    {
        float4 ra = *(const float4*)Aptr;
        float4 rw = *(const float4*)Wptr;
        As[0][lk + 0][lrow] = ra.x; As[0][lk + 1][lrow] = ra.y;
        As[0][lk + 2][lrow] = ra.z; As[0][lk + 3][lrow] = ra.w;
        Ws[0][lk + 0][lrow] = rw.x; Ws[0][lk + 1][lrow] = rw.y;
        Ws[0][lk + 2][lrow] = rw.z; Ws[0][lk + 3][lrow] = rw.w;
    }
    __syncthreads();

    constexpr int NKT = D_ / BK;
    int buf = 0;
    for (int kt = 1; kt <= NKT; kt++) {
        float4 na, nw;
        if (kt < NKT) {
            na = *(const float4*)(Aptr + kt * BK);
            nw = *(const float4*)(Wptr + kt * BK);
        }
#pragma unroll
        for (int k = 0; k < BK; k++) {
            float4 a0 = *(const float4*)&As[buf][k][wm + trow];
            float4 a1 = *(const float4*)&As[buf][k][wm + 16 + trow];
            ulonglong2 w0 = *(const ulonglong2*)&Ws[buf][k][wn + tcol];
            ulonglong2 w1 = *(const ulonglong2*)&Ws[buf][k][wn + 32 + tcol];
            float av[8] = {a0.x, a0.y, a0.z, a0.w, a1.x, a1.y, a1.z, a1.w};
#pragma unroll
            for (int i = 0; i < 8; i++) {
                unsigned long long ad = dup2(av[i]);
                fma2(acc2[i][0], ad, w0.x);
                fma2(acc2[i][1], ad, w0.y);
                fma2(acc2[i][2], ad, w1.x);
                fma2(acc2[i][3], ad, w1.y);
            }
        }
        if (kt < NKT) {
            int nb = buf ^ 1;
            As[nb][lk + 0][lrow] = na.x; As[nb][lk + 1][lrow] = na.y;
            As[nb][lk + 2][lrow] = na.z; As[nb][lk + 3][lrow] = na.w;
            Ws[nb][lk + 0][lrow] = nw.x; Ws[nb][lk + 1][lrow] = nw.y;
            Ws[nb][lk + 2][lrow] = nw.z; Ws[nb][lk + 3][lrow] = nw.w;
        }
        __syncthreads();
        buf ^= 1;
    }

    float4 bb0 = *(const float4*)&bias[n0 + wn + tcol];
    float4 bb1 = *(const float4*)&bias[n0 + wn + 32 + tcol];
#pragma unroll
    for (int i = 0; i < 8; i++) {
        int mi = wm + ((i < 4) ? (trow + i) : (16 + trow + i - 4));
        float* cp = C + (size_t)(m0 + mi) * D_ + n0;
        float2 p0 = unpk(acc2[i][0]);
        float2 p1 = unpk(acc2[i][1]);
        float2 p2 = unpk(acc2[i][2]);
        float2 p3 = unpk(acc2[i][3]);
        float4 o0 = make_float4(p0.x + bb0.x, p0.y + bb0.y,
                                p1.x + bb0.z, p1.y + bb0.w);
        float4 o1 = make_float4(p2.x + bb1.x, p2.y + bb1.y,
                                p3.x + bb1.z, p3.y + bb1.w);
        *(float4*)(cp + wn + tcol) = o0;
        *(float4*)(cp + wn + 32 + tcol) = o1;
    }
}

// ---------------------------------------------------------------------------
// h0 -> H[0]
// ---------------------------------------------------------------------------
__global__ void copy_h0_kernel(const float* __restrict__ h0, float* __restrict__ H)
{
    int i = blockIdx.x * blockDim.x + threadIdx.x;
    if (i < B_ * D_) H[i] = h0[i];
}

// ---------------------------------------------------------------------------
// Persistent recurrent scan, round-6 structure.
// 128 CTAs x 1024 threads (32 warps = 8/SMSP for issue-efficiency).
// CTA owns 8 columns; weights cached once as interleaved (R_h,R_delta) float2
// so one fma.rn.f32x2 drives both dot products. Each warp owns a 32-wide
// K-slice: stages its own h slice (coalesced LDG->STS, syncwarp only), then
// computes all 8 columns with broadcast weight LDS. Two-phase partial
// reduction (warps 16-31 publish, 0-15 fold with add.rn.f32x2) keeps SMEM
// within budget; 256 epilogue threads apply gates; master+release barrier.
// ---------------------------------------------------------------------------
constexpr int NCTA = 128;
constexpr int JC = 8;                        // columns per CTA
constexpr int SB_ = 1024;                    // threads per CTA
constexpr int H4S = 257;                     // float4 stride per batch row
constexpr int WVD_F = JC * D_ * 2;           // 16384 floats (interleaved pairs)
constexpr int HS_F = B_ * H4S * 4;           // 32896 floats
constexpr int RED_ROW = 33;                  // u64 per row (padded)
constexpr int RED_F = 16 * JC * RED_ROW * 2; // 8448 floats
constexpr int SMEM_FLOATS = WVD_F + HS_F + RED_F;
constexpr int SMEM_BYTES = SMEM_FLOATS * 4;  // 230912 B

__device__ volatile unsigned g_arrive[NCTA * 32];  // one flag per CTA, 128B apart
__device__ volatile unsigned g_release;

__global__ void __launch_bounds__(SB_, 1) scan_kernel(
    const float* __restrict__ x,
    const float* __restrict__ Rh,
    const float* __restrict__ Rd,
    const float* __restrict__ bgate,
    float* __restrict__ out,
    float* __restrict__ H)
{
    extern __shared__ float sm[];
    float2* wvd2 = (float2*)sm;                       // [JC][D_] (Rh,Rd) pairs
    const ulonglong2* wvd_u2 = (const ulonglong2*)sm; // same, 2 k's per load
    float*  hsf = sm + WVD_F;                         // h as [B][H4S*4] floats
    float4* hs4 = (float4*)hsf;
    unsigned long long* red2 = (unsigned long long*)(sm + WVD_F + HS_F);

    const float* __restrict__ xr = g_scratch[0];
    const float* __restrict__ xw = g_scratch[1];

    const int cta = blockIdx.x;
    const int tid = threadIdx.x;
    const int j0 = cta * JC;

    // Cache this CTA's weights once, interleaved (Rh, Rd).
    for (int i = tid; i < JC * D_; i += SB_) {
        int j = i >> 10, k = i & 1023;
        wvd2[i] = make_float2(Rh[(size_t)(j0 + j) * D_ + k],
                              Rd[(size_t)(j0 + j) * D_ + k]);
    }
    __syncthreads();

    const int warp  = tid >> 5;      // 0..31, owns K-slice [warp*32, warp*32+32)
    const int b     = tid & 31;      // lane -> batch
    const int qbase = warp * 8;      // float4 index base of this warp's K-slice

    // epilogue mapping (tid < 256): column ej, batch eb
    const int ej = tid & 7;
    const int eb = tid >> 3;
    const int jg = j0 + ej;
    float bg = 0.f;
    if (tid < 256) bg = bgate[jg];

    for (int t = 0; t < T_; t++) {
        const size_t tb = (size_t)t * B_ * D_;

        // ---- prefetch epilogue inputs early (latency hidden by compute) ----
        float pre_xr = 0.f, pre_xw = 0.f, pre_x = 0.f;
        const size_t eidx = tb + (size_t)eb * D_ + jg;
        if (tid < 256) {
            pre_xr = __ldg(xr + eidx);
            pre_xw = __ldg(xw + eidx);
            pre_x  = __ldg(x + eidx);
        }

        // ---- per-warp h staging: this warp's K-slice, all batches ----
        const float4* hp = (const float4*)(H + tb);
#pragma unroll
        for (int it = 0; it < 8; it++) {
            int idx = it * 32 + b;          // 0..255
            int b2  = idx >> 3;             // batch
            int qq  = idx & 7;              // f4 within slice
            float4 v = __ldcg(hp + b2 * 256 + qbase + qq);
            hs4[b2 * H4S + qbase + qq] = v;
        }
        __syncwarp();

        // ---- compute: 8 columns x 2 matrices, this warp's 32 k's ----
        unsigned long long acc2[JC];
#pragma unroll
        for (int j = 0; j < JC; j++) acc2[j] = 0ull;

#pragma unroll
        for (int qq = 0; qq < 8; qq++) {
            int q = qbase + qq;
            float4 h4 = hs4[b * H4S + q];
            unsigned long long hx = dup2(h4.x);
            unsigned long long hy = dup2(h4.y);
            unsigned long long hz = dup2(h4.z);
            unsigned long long hw = dup2(h4.w);
#pragma unroll
            for (int j = 0; j < JC; j++) {
                ulonglong2 wA = wvd_u2[j * 512 + 2 * q];      // k=4q,4q+1
                ulonglong2 wB = wvd_u2[j * 512 + 2 * q + 1];  // k=4q+2,4q+3
                fma2(acc2[j], hx, wA.x);
                fma2(acc2[j], hy, wA.y);
                fma2(acc2[j], hz, wB.x);
                fma2(acc2[j], hw, wB.y);
            }
        }

        // ---- two-phase split-K reduction: 32 -> 16 partials ----
        if (warp >= 16) {
#pragma unroll
            for (int j = 0; j < JC; j++)
                red2[((warp - 16) * JC + j) * RED_ROW + b] = acc2[j];
        }
        __syncthreads();
        if (warp < 16) {
#pragma unroll
            for (int j = 0; j < JC; j++) {
                add2(acc2[j], red2[(warp * JC + j) * RED_ROW + b]);
                red2[(warp * JC + j) * RED_ROW + b] = acc2[j];
            }
        }
        __syncthreads();

        // ---- epilogue: reduce 16 partials, gates, write out & H[t+1] ----
        if (tid < 256) {
            float sv = pre_xr, sd = pre_xw;
#pragma unroll
            for (int w = 0; w < 16; w++) {
                float2 p = unpk(red2[(w * JC + ej) * RED_ROW + eb]);
                sv += p.x;
                sd += p.y;
            }
            float hprev = hsf[eb * (H4S * 4) + jg];
            float delta = 1.f / (1.f + __expf(-sd));
            float hv    = tanhf(sv);
            float hn    = hprev + delta * (hv - hprev);  // (1-d)*hp + d*tanh(v)
            float g     = hn + pre_x + bg;
            float sil   = g / (1.f + __expf(-g));        // silu(g)
            out[eidx] = hn * sil;
            H[eidx + (size_t)B_ * D_] = hn;              // H[t+1]
            __threadfence();                             // order H before flag
        }

        if (t == T_ - 1) break;

        // ---- grid-wide barrier: flag array + master warp + release word ----
        __syncthreads();
        const unsigned want = (unsigned)(t + 1);
        if (tid == 0) g_arrive[cta << 5] = want;
        if (cta == 0 && tid >= 32 && tid < 64) {
            int l = tid - 32;                 // each lane watches 4 CTA flags
            bool ok;
            do {
                ok = (g_arrive[(l * 4 + 0) << 5] == want)
                  && (g_arrive[(l * 4 + 1) << 5] == want)
                  && (g_arrive[(l * 4 + 2) << 5] == want)
                  && (g_arrive[(l * 4 + 3) << 5] == want);
            } while (!__all_sync(0xffffffffu, ok));
            if (l == 0) { __threadfence(); g_release = want; }
        }
        if (tid == 0) {
            while (g_release != want) { __nanosleep(32); }
        }
        __syncthreads();
    }
}

// ---------------------------------------------------------------------------
// Launch
// Inputs (metadata order): x, h0, R_h, R_x, R_delta, W_delta, b, b_delta, b_gate
// Output: outputs [T,B,D] followed by h [T+1,B,D], fp32.
// ---------------------------------------------------------------------------
extern "C" void kernel_launch(void* const* d_in, const int* in_sizes, int n_in,
                              void* d_out, int out_size)
{
    const float* x       = (const float*)d_in[0];
    const float* h0      = (const float*)d_in[1];
    const float* R_h     = (const float*)d_in[2];
    const float* R_x     = (const float*)d_in[3];
    const float* R_delta = (const float*)d_in[4];
    const float* W_delta = (const float*)d_in[5];
    const float* b       = (const float*)d_in[6];
    const float* b_delta = (const float*)d_in[7];
    const float* b_gate  = (const float*)d_in[8];

    float* out = (float*)d_out;
    float* H   = out + (size_t)T_ * B_ * D_;   // h region: [T+1, B, D]

    cudaFuncSetAttribute(scan_kernel,
                         cudaFuncAttributeMaxDynamicSharedMemorySize, SMEM_BYTES);

    dim3 ggrid(D_ / BN, M_ / BM, 2);
    gemm_bias_kernel<<<ggrid, 256>>>(x, R_x, W_delta, b, b_delta);
    copy_h0_kernel<<<(B_ * D_ + 255) / 256, 256>>>(h0, H);
    scan_kernel<<<NCTA, SB_, SMEM_BYTES>>>(x, R_h, R_delta, b_gate, out, H);
}

// round 11
// speedup vs baseline: 1.3602x; 1.3602x over previous
#include <cuda_runtime.h>
#include <cstdint>

// Problem constants
constexpr int T_ = 1024;
constexpr int B_ = 32;
constexpr int D_ = 1024;
constexpr int M_ = T_ * B_;        // 32768 rows for the precompute GEMMs

// Scratch for precomputed xRx ([0]) and xWd ([1])
__device__ float g_scratch[2][(size_t)M_ * D_];

// ---------------------------------------------------------------------------
// Packed f32x2 helpers (sm_103a): one instruction = two fp32 FMAs/ADDs.
// ---------------------------------------------------------------------------
__device__ __forceinline__ void fma2(unsigned long long& d,
                                     unsigned long long a,
                                     unsigned long long b) {
    asm("fma.rn.f32x2 %0, %1, %2, %0;" : "+l"(d) : "l"(a), "l"(b));
}
__device__ __forceinline__ void add2(unsigned long long& d,
                                     unsigned long long a) {
    asm("add.rn.f32x2 %0, %0, %1;" : "+l"(d) : "l"(a));
}
__device__ __forceinline__ unsigned long long dup2(float x) {
    unsigned long long r;
    asm("mov.b64 %0, {%1, %1};" : "=l"(r) : "f"(x));
    return r;
}
__device__ __forceinline__ float2 unpk(unsigned long long v) {
    float2 r;
    asm("mov.b64 {%0, %1}, %2;" : "=f"(r.x), "=f"(r.y) : "l"(v));
    return r;
}

// ---------------------------------------------------------------------------
// Grid barrier primitives: release-reduction arrive + acquire poll.
// ---------------------------------------------------------------------------
__device__ unsigned g_ctr;   // reset to 0 by copy_h0_kernel each launch

__device__ __forceinline__ void arrive_release(unsigned* p) {
    asm volatile("red.release.gpu.global.add.u32 [%0], 1;"
                 :: "l"(p) : "memory");
}
__device__ __forceinline__ unsigned ld_acquire(const unsigned* p) {
    unsigned v;
    asm volatile("ld.acquire.gpu.global.u32 %0, [%1];" : "=r"(v) : "l"(p)
                 : "memory");
    return v;
}

// ---------------------------------------------------------------------------
// Precompute GEMM: C[m][n] = sum_k A[m][k] * W[n][k] + bias[n]
// 128x128 tile, k-tile 8, 256 threads, 8x8 microtile held as 8x4 f32x2
// packed accumulators, double-buffered SMEM. blockIdx.z selects the
// (W, bias, C) pair so both GEMMs share A through L2.
// ---------------------------------------------------------------------------
constexpr int BM = 128, BN = 128, BK = 8;

__global__ void __launch_bounds__(256) gemm_bias_kernel(
    const float* __restrict__ A,
    const float* __restrict__ W0, const float* __restrict__ W1,
    const float* __restrict__ b0, const float* __restrict__ b1)
{
    const float* __restrict__ W    = blockIdx.z ? W1 : W0;
    const float* __restrict__ bias = blockIdx.z ? b1 : b0;
    float* __restrict__ C = g_scratch[blockIdx.z];

    __shared__ float As[2][BK][BM];
    __shared__ float Ws[2][BK][BN];

    const int m0 = blockIdx.y * BM;
    const int n0 = blockIdx.x * BN;
    const int tid = threadIdx.x;

    const int lrow = tid >> 1;            // 0..127
    const int lk   = (tid & 1) << 2;      // 0 or 4

    const int wid  = tid >> 5;
    const int lane = tid & 31;
    const int wm   = (wid & 3) * 32;
    const int wn   = (wid >> 2) * 64;
    const int trow = (lane >> 3) << 2;    // 0,4,8,12
    const int tcol = (lane & 7) << 2;     // 0..28

    unsigned long long acc2[8][4];
#pragma unroll
    for (int i = 0; i < 8; i++)
#pragma unroll
        for (int p = 0; p < 4; p++) acc2[i][p] = 0ull;

    const float* Aptr = A + (size_t)(m0 + lrow) * D_ + lk;
    const float* Wptr = W + (size_t)(n0 + lrow) * D_ + lk;

    {
        float4 ra = *(const float4*)Aptr;
        float4 rw = *(const float4*)Wptr;
        As[0][lk + 0][lrow] = ra.x; As[0][lk + 1][lrow] = ra.y;
        As[0][lk + 2][lrow] = ra.z; As[0][lk + 3][lrow] = ra.w;
        Ws[0][lk + 0][lrow] = rw.x; Ws[0][lk + 1][lrow] = rw.y;
        Ws[0][lk + 2][lrow] = rw.z; Ws[0][lk + 3][lrow] = rw.w;
    }
    __syncthreads();

    constexpr int NKT = D_ / BK;
    int buf = 0;
    for (int kt = 1; kt <= NKT; kt++) {
        float4 na, nw;
        if (kt < NKT) {
            na = *(const float4*)(Aptr + kt * BK);
            nw = *(const float4*)(Wptr + kt * BK);
        }
#pragma unroll
        for (int k = 0; k < BK; k++) {
            float4 a0 = *(const float4*)&As[buf][k][wm + trow];
            float4 a1 = *(const float4*)&As[buf][k][wm + 16 + trow];
            ulonglong2 w0 = *(const ulonglong2*)&Ws[buf][k][wn + tcol];
            ulonglong2 w1 = *(const ulonglong2*)&Ws[buf][k][wn + 32 + tcol];
            float av[8] = {a0.x, a0.y, a0.z, a0.w, a1.x, a1.y, a1.z, a1.w};
#pragma unroll
            for (int i = 0; i < 8; i++) {
                unsigned long long ad = dup2(av[i]);
                fma2(acc2[i][0], ad, w0.x);
                fma2(acc2[i][1], ad, w0.y);
                fma2(acc2[i][2], ad, w1.x);
                fma2(acc2[i][3], ad, w1.y);
            }
        }
        if (kt < NKT) {
            int nb = buf ^ 1;
            As[nb][lk + 0][lrow] = na.x; As[nb][lk + 1][lrow] = na.y;
            As[nb][lk + 2][lrow] = na.z; As[nb][lk + 3][lrow] = na.w;
            Ws[nb][lk + 0][lrow] = nw.x; Ws[nb][lk + 1][lrow] = nw.y;
            Ws[nb][lk + 2][lrow] = nw.z; Ws[nb][lk + 3][lrow] = nw.w;
        }
        __syncthreads();
        buf ^= 1;
    }

    float4 bb0 = *(const float4*)&bias[n0 + wn + tcol];
    float4 bb1 = *(const float4*)&bias[n0 + wn + 32 + tcol];
#pragma unroll
    for (int i = 0; i < 8; i++) {
        int mi = wm + ((i < 4) ? (trow + i) : (16 + trow + i - 4));
        float* cp = C + (size_t)(m0 + mi) * D_ + n0;
        float2 p0 = unpk(acc2[i][0]);
        float2 p1 = unpk(acc2[i][1]);
        float2 p2 = unpk(acc2[i][2]);
        float2 p3 = unpk(acc2[i][3]);
        float4 o0 = make_float4(p0.x + bb0.x, p0.y + bb0.y,
                                p1.x + bb0.z, p1.y + bb0.w);
        float4 o1 = make_float4(p2.x + bb1.x, p2.y + bb1.y,
                                p3.x + bb1.z, p3.y + bb1.w);
        *(float4*)(cp + wn + tcol) = o0;
        *(float4*)(cp + wn + 32 + tcol) = o1;
    }
}

// ---------------------------------------------------------------------------
// h0 -> H[0]; also resets the scan's grid-barrier counter for this launch
// (required for deterministic graph replays).
// ---------------------------------------------------------------------------
__global__ void copy_h0_kernel(const float* __restrict__ h0, float* __restrict__ H)
{
    int i = blockIdx.x * blockDim.x + threadIdx.x;
    if (i < B_ * D_) H[i] = h0[i];
    if (i == 0) g_ctr = 0u;
}

// ---------------------------------------------------------------------------
// Persistent recurrent scan (round-9).
// 128 CTAs x 512 threads (round-5 compute core — measured best).
// CTA owns 8 columns; weights cached once as interleaved (R_h,R_delta) float2
// so one fma.rn.f32x2 drives both dot products. Each of 16 warps owns a
// 64-wide K-slice: stages its own h slice (coalesced LDG->STS, syncwarp
// only), computes all 8 columns with broadcast weight LDS, publishes packed
// partials. 256 epilogue threads fold 16 partials (packed f32x2, 2 chains),
// apply gates, write out & H[t+1].
// Grid barrier: single release-reduction counter + acquire polling
// (1 L2 hop instead of arrive->master->release; no full MEMBAR).
// ---------------------------------------------------------------------------
constexpr int NCTA = 128;
constexpr int JC = 8;                        // columns per CTA
constexpr int SB_ = 512;                     // threads per CTA
constexpr int H4S = 257;                     // float4 stride per batch row
constexpr int WVD_F = JC * D_ * 2;           // 16384 floats (interleaved pairs)
constexpr int HS_F = B_ * H4S * 4;           // 32896 floats
constexpr int RED_ROW = 33;                  // u64 per row (padded)
constexpr int RED_F = 16 * JC * RED_ROW * 2; // 8448 floats
constexpr int SMEM_FLOATS = WVD_F + HS_F + RED_F;
constexpr int SMEM_BYTES = SMEM_FLOATS * 4;  // 230912 B

__global__ void __launch_bounds__(SB_, 1) scan_kernel(
    const float* __restrict__ x,
    const float* __restrict__ Rh,
    const float* __restrict__ Rd,
    const float* __restrict__ bgate,
    float* __restrict__ out,
    float* __restrict__ H)
{
    extern __shared__ float sm[];
    float2* wvd2 = (float2*)sm;                       // [JC][D_] (Rh,Rd) pairs
    const ulonglong2* wvd_u2 = (const ulonglong2*)sm; // same, 2 k's per load
    float*  hsf = sm + WVD_F;                         // h as [B][H4S*4] floats
    float4* hs4 = (float4*)hsf;
    unsigned long long* red2 = (unsigned long long*)(sm + WVD_F + HS_F);

    const float* __restrict__ xr = g_scratch[0];
    const float* __restrict__ xw = g_scratch[1];

    const int cta = blockIdx.x;
    const int tid = threadIdx.x;
    const int j0 = cta * JC;

    // Cache this CTA's weights once, interleaved (Rh, Rd).
    for (int i = tid; i < JC * D_; i += SB_) {
        int j = i >> 10, k = i & 1023;
        wvd2[i] = make_float2(Rh[(size_t)(j0 + j) * D_ + k],
                              Rd[(size_t)(j0 + j) * D_ + k]);
    }
    __syncthreads();

    const int warp  = tid >> 5;      // 0..15, owns K-slice [warp*64, warp*64+64)
    const int b     = tid & 31;      // lane -> batch
    const int qbase = warp * 16;     // float4 index base of this warp's K-slice

    // epilogue mapping (tid < 256): column ej, batch eb
    const int ej = tid & 7;
    const int eb = tid >> 3;
    const int jg = j0 + ej;
    float bg = 0.f;
    if (tid < 256) bg = bgate[jg];

    for (int t = 0; t < T_; t++) {
        const size_t tb = (size_t)t * B_ * D_;

        // ---- prefetch epilogue inputs early (latency hidden by compute) ----
        float pre_xr = 0.f, pre_xw = 0.f, pre_x = 0.f;
        const size_t eidx = tb + (size_t)eb * D_ + jg;
        if (tid < 256) {
            pre_xr = __ldg(xr + eidx);
            pre_xw = __ldg(xw + eidx);
            pre_x  = __ldg(x + eidx);
        }

        // ---- per-warp h staging: this warp's K-slice, all batches ----
        const float4* hp = (const float4*)(H + tb);
#pragma unroll
        for (int it = 0; it < 16; it++) {
            int idx = it * 32 + b;          // coalesced
            int b2  = idx >> 4;
            int qq  = idx & 15;
            float4 v = __ldcg(hp + b2 * 256 + qbase + qq);
            hs4[b2 * H4S + qbase + qq] = v;
        }
        __syncwarp();

        // ---- compute: 8 columns x 2 matrices, this warp's 64 k's ----
        unsigned long long acc2[JC];
#pragma unroll
        for (int j = 0; j < JC; j++) acc2[j] = 0ull;

#pragma unroll 4
        for (int qq = 0; qq < 16; qq++) {
            int q = qbase + qq;
            float4 h4 = hs4[b * H4S + q];
            unsigned long long hx = dup2(h4.x);
            unsigned long long hy = dup2(h4.y);
            unsigned long long hz = dup2(h4.z);
            unsigned long long hw = dup2(h4.w);
#pragma unroll
            for (int j = 0; j < JC; j++) {
                ulonglong2 wA = wvd_u2[j * 512 + 2 * q];      // k=4q,4q+1
                ulonglong2 wB = wvd_u2[j * 512 + 2 * q + 1];  // k=4q+2,4q+3
                fma2(acc2[j], hx, wA.x);
                fma2(acc2[j], hy, wA.y);
                fma2(acc2[j], hz, wB.x);
                fma2(acc2[j], hw, wB.y);
            }
        }

        // ---- store split-K partials ----
#pragma unroll
        for (int j = 0; j < JC; j++)
            red2[(warp * JC + j) * RED_ROW + b] = acc2[j];
        __syncthreads();

        // ---- epilogue: fold 16 partials (packed, 2 chains), gates, write ----
        if (tid < 256) {
            unsigned long long sA = 0ull, sB = 0ull;
#pragma unroll
            for (int w = 0; w < 16; w += 2) {
                add2(sA, red2[((w + 0) * JC + ej) * RED_ROW + eb]);
                add2(sB, red2[((w + 1) * JC + ej) * RED_ROW + eb]);
            }
            add2(sA, sB);
            float2 p = unpk(sA);
            float sv = pre_xr + p.x;
            float sd = pre_xw + p.y;

            float hprev = hsf[eb * (H4S * 4) + jg];
            float delta = 1.f / (1.f + __expf(-sd));
            float hv    = tanhf(sv);
            float hn    = hprev + delta * (hv - hprev);  // (1-d)*hp + d*tanh(v)
            float g     = hn + pre_x + bg;
            float sil   = g / (1.f + __expf(-g));        // silu(g)
            out[eidx] = hn * sil;
            H[eidx + (size_t)B_ * D_] = hn;              // H[t+1]
        }

        if (t == T_ - 1) break;

        // ---- grid barrier: release-red counter + acquire poll ----
        __syncthreads();                   // all H[t+1] stores issued
        if (tid == 0) {
            arrive_release(&g_ctr);
            const unsigned want = (unsigned)(NCTA * (t + 1));
            while ((int)(ld_acquire(&g_ctr) - want) < 0) { }
        }
        __syncthreads();
    }
}

// ---------------------------------------------------------------------------
// Launch
// Inputs (metadata order): x, h0, R_h, R_x, R_delta, W_delta, b, b_delta, b_gate
// Output: outputs [T,B,D] followed by h [T+1,B,D], fp32.
// ---------------------------------------------------------------------------
extern "C" void kernel_launch(void* const* d_in, const int* in_sizes, int n_in,
                              void* d_out, int out_size)
{
    const float* x       = (const float*)d_in[0];
    const float* h0      = (const float*)d_in[1];
    const float* R_h     = (const float*)d_in[2];
    const float* R_x     = (const float*)d_in[3];
    const float* R_delta = (const float*)d_in[4];
    const float* W_delta = (const float*)d_in[5];
    const float* b       = (const float*)d_in[6];
    const float* b_delta = (const float*)d_in[7];
    const float* b_gate  = (const float*)d_in[8];

    float* out = (float*)d_out;
    float* H   = out + (size_t)T_ * B_ * D_;   // h region: [T+1, B, D]

    cudaFuncSetAttribute(scan_kernel,
                         cudaFuncAttributeMaxDynamicSharedMemorySize, SMEM_BYTES);

    dim3 ggrid(D_ / BN, M_ / BM, 2);
    gemm_bias_kernel<<<ggrid, 256>>>(x, R_x, W_delta, b, b_delta);
    copy_h0_kernel<<<(B_ * D_ + 255) / 256, 256>>>(h0, H);
    scan_kernel<<<NCTA, SB_, SMEM_BYTES>>>(x, R_h, R_delta, b_gate, out, H);
}